// round 12
// baseline (speedup 1.0000x reference)
#include <cuda_runtime.h>
#include <math.h>

#define DD   256
#define DD3  768
#define OBJ_FLAG 0x40000000

// ---------------- device scratch ----------------
__device__ float g_sub[DD];                 // seed subject embedding
__device__ float g_gi0[DD3];                // enc @ W_ih.T + b_ih
__device__ float g_gh0[DD3];                // sub @ W_hh.T + b_hh
__device__ float g_gi[DD3];                 // r0 @ W_ih.T + b_ih
__device__ float g_rj[1024 * DD];           // GRU output per relation [R,256]
__device__ float g_objTable[1024 * DD];     // obj embedding per relation [R,256]
__device__ int   g_src[1 << 19];            // node -> source descriptor

__device__ __forceinline__ float sigm(float x) { return 1.0f / (1.0f + expf(-x)); }

// ---------------- K1: sub + gi0 + gh0 in ONE kernel ----------------
// 48 blocks x 512 threads. Phase 1: every block recomputes sub into smem
// (sub_W = 256KB; 48 blocks = 12MB L2 - cheap). Phase 2: 32 rows/block of the
// concatenated [gi0(768); gh0(768)] row space.
__global__ void __launch_bounds__(512) matvec1_kernel(
    const float* __restrict__ mask, const float* __restrict__ enc,
    const float* __restrict__ sub_W, const float* __restrict__ sub_b,
    const float* __restrict__ W_ih, const float* __restrict__ W_hh,
    const float* __restrict__ b_ih, const float* __restrict__ b_hh)
{
    __shared__ float4 xm[64], xe[64];
    __shared__ float subs[DD];
    __shared__ float part[512];
    int tid = threadIdx.x;

    if (tid < 64) { xm[tid] = ((const float4*)mask)[tid]; xe[tid] = ((const float4*)enc)[tid]; }
    __syncthreads();

    // --- phase 1: sub = tanh(sub_W @ mask + sub_b), 2 threads per row ---
    {
        int row = tid >> 1, half = tid & 1;
        const float4* w = (const float4*)(sub_W + (size_t)row * DD) + half * 32;
        float acc = 0.f;
        #pragma unroll 8
        for (int i = 0; i < 32; i++) {
            float4 wv = w[i], x4 = xm[half * 32 + i];
            acc += wv.x * x4.x + wv.y * x4.y + wv.z * x4.z + wv.w * x4.w;
        }
        part[tid] = acc;
    }
    __syncthreads();
    if ((tid & 1) == 0) {
        int row = tid >> 1;
        subs[row] = tanhf(part[tid] + part[tid + 1] + sub_b[row]);
    }
    __syncthreads();
    if (blockIdx.x == 0 && tid < DD) g_sub[tid] = subs[tid];

    // --- phase 2: 32 rows of [gi0; gh0], 16-lane group per row ---
    int warp = tid >> 5, lane = tid & 31;
    int grp = lane >> 4, l16 = lane & 15;
    int gr = blockIdx.x * 32 + warp * 2 + grp;   // 0..1535
    bool isH = gr >= DD3;
    int row = isH ? gr - DD3 : gr;
    const float4* w = (const float4*)((isH ? W_hh : W_ih) + (size_t)row * DD);
    const float4* xv = isH ? (const float4*)subs : xe;
    float acc = 0.f;
    #pragma unroll
    for (int i = 0; i < 4; i++) {
        int k = l16 + i * 16;
        float4 wv = w[k], x4 = xv[k];
        acc += wv.x * x4.x + wv.y * x4.y + wv.z * x4.z + wv.w * x4.w;
    }
    #pragma unroll
    for (int o = 8; o > 0; o >>= 1) acc += __shfl_down_sync(~0u, acc, o);
    if (l16 == 0) {
        if (isH) g_gh0[row] = acc + b_hh[row];
        else     g_gi0[row] = acc + b_ih[row];
    }
}

// ---------------- matvecD: r0 (recomputed) then gi = W_ih @ r0 + b_ih ----------------
__global__ void __launch_bounds__(256) matvecD_kernel(
    const float* __restrict__ W_ih, const float* __restrict__ b_ih)
{
    __shared__ float r0s[DD];
    int tid = threadIdx.x, lane = tid & 31, warp = tid >> 5;
    {
        float gi_r = g_gi0[tid],          gh_r = g_gh0[tid];
        float gi_z = g_gi0[DD + tid],     gh_z = g_gh0[DD + tid];
        float gi_n = g_gi0[2 * DD + tid], gh_n = g_gh0[2 * DD + tid];
        float r = sigm(gi_r + gh_r);
        float z = sigm(gi_z + gh_z);
        float n = tanhf(gi_n + r * gh_n);
        r0s[tid] = (1.0f - z) * n + z * g_sub[tid];
    }
    __syncthreads();
    int row = blockIdx.x * 8 + warp;             // 0..767
    const float4* w = (const float4*)(W_ih + (size_t)row * DD);
    const float4* xv = (const float4*)r0s;
    float acc = 0.f;
    #pragma unroll
    for (int i = 0; i < 2; i++) {
        int k = lane + i * 32;
        float4 wv = w[k], x4 = xv[k];
        acc += wv.x * x4.x + wv.y * x4.y + wv.z * x4.z + wv.w * x4.w;
    }
    #pragma unroll
    for (int o = 16; o > 0; o >>= 1) acc += __shfl_down_sync(~0u, acc, o);
    if (lane == 0) g_gi[row] = acc + b_ih[row];
}

// ---------------- scatter: resolve per-edge source descriptor ----------------
__global__ void __launch_bounds__(512) scatter_kernel(
    const int* __restrict__ tail_ids, const int* __restrict__ tails_state,
    const int* __restrict__ origin_ids, const int* __restrict__ rel_ids, int E)
{
    int e = blockIdx.x * blockDim.x + threadIdx.x;
    if (e >= E) return;
    int code = (__ldg(tails_state + e) == 1) ? __ldg(origin_ids + e)
                                             : (__ldg(rel_ids + e) | OBJ_FLAG);
    g_src[__ldg(tail_ids + e)] = code;
}

// ---------------- relgemm (lean R7 version): gh GEMM (3 gates) + GRU gates -> g_rj ----------------
__global__ void __launch_bounds__(256) relgemm_kernel(
    const float* __restrict__ rel_table, const float* __restrict__ W_hh,
    const float* __restrict__ b_hh, int R)
{
    __shared__ float As[32][36];
    __shared__ float Bs[3][32][68];
    int tid = threadIdx.x;
    int tx = tid & 15, ty = tid >> 4;
    int rbase = blockIdx.y * 32;
    int j0 = blockIdx.x * 64;
    float acc[3][2][4] = {};

    for (int k0 = 0; k0 < DD; k0 += 32) {
        {   // A tile: rel_table rows
            int ar = tid >> 3;
            int ac = (tid & 7) << 2;
            int gr = rbase + ar;
            float4 av = (gr < R) ? *(const float4*)(rel_table + (size_t)gr * DD + k0 + ac)
                                 : make_float4(0.f, 0.f, 0.f, 0.f);
            *(float4*)&As[ar][ac] = av;
        }
        #pragma unroll
        for (int i = 0; i < 6; i++) {     // B tiles: 192 j-rows x 32 k, transposed store
            int idx = tid + i * 256;
            int jrow = idx >> 3;          // 0..191
            int kc = (idx & 7) << 2;
            int gate = jrow >> 6;
            int jj = jrow & 63;
            float4 w4 = *(const float4*)(W_hh + (size_t)(gate * DD + j0 + jj) * DD + k0 + kc);
            Bs[gate][kc + 0][jj] = w4.x;
            Bs[gate][kc + 1][jj] = w4.y;
            Bs[gate][kc + 2][jj] = w4.z;
            Bs[gate][kc + 3][jj] = w4.w;
        }
        __syncthreads();
        #pragma unroll
        for (int kk = 0; kk < 32; kk++) {
            float a0 = As[ty][kk];
            float a1 = As[ty + 16][kk];
            #pragma unroll
            for (int g = 0; g < 3; g++) {
                float4 b = *(const float4*)&Bs[g][kk][tx * 4];
                acc[g][0][0] = fmaf(a0, b.x, acc[g][0][0]); acc[g][0][1] = fmaf(a0, b.y, acc[g][0][1]);
                acc[g][0][2] = fmaf(a0, b.z, acc[g][0][2]); acc[g][0][3] = fmaf(a0, b.w, acc[g][0][3]);
                acc[g][1][0] = fmaf(a1, b.x, acc[g][1][0]); acc[g][1][1] = fmaf(a1, b.y, acc[g][1][1]);
                acc[g][1][2] = fmaf(a1, b.z, acc[g][1][2]); acc[g][1][3] = fmaf(a1, b.w, acc[g][1][3]);
            }
        }
        __syncthreads();
    }

    // epilogue: gh + bias -> GRU combine -> rj
    int col = j0 + tx * 4;
    float4 bhr = *(const float4*)(b_hh + col);
    float4 bhz = *(const float4*)(b_hh + DD + col);
    float4 bhn = *(const float4*)(b_hh + 2 * DD + col);
    float4 gir = *(const float4*)(g_gi + col);
    float4 giz = *(const float4*)(g_gi + DD + col);
    float4 gin = *(const float4*)(g_gi + 2 * DD + col);
    #pragma unroll
    for (int i = 0; i < 2; i++) {
        int r = rbase + ty + i * 16;
        if (r < R) {
            float4 h = *(const float4*)(rel_table + (size_t)r * DD + col);
            float ghr[4] = { acc[0][i][0] + bhr.x, acc[0][i][1] + bhr.y, acc[0][i][2] + bhr.z, acc[0][i][3] + bhr.w };
            float ghz[4] = { acc[1][i][0] + bhz.x, acc[1][i][1] + bhz.y, acc[1][i][2] + bhz.z, acc[1][i][3] + bhz.w };
            float ghn[4] = { acc[2][i][0] + bhn.x, acc[2][i][1] + bhn.y, acc[2][i][2] + bhn.z, acc[2][i][3] + bhn.w };
            float gi_r[4] = { gir.x, gir.y, gir.z, gir.w };
            float gi_z[4] = { giz.x, giz.y, giz.z, giz.w };
            float gi_n[4] = { gin.x, gin.y, gin.z, gin.w };
            float hh[4] = { h.x, h.y, h.z, h.w };
            float o[4];
            #pragma unroll
            for (int q = 0; q < 4; q++) {
                float rr = sigm(gi_r[q] + ghr[q]);
                float zz = sigm(gi_z[q] + ghz[q]);
                float nn = tanhf(gi_n[q] + rr * ghn[q]);
                o[q] = (1.f - zz) * nn + zz * hh[q];
            }
            *(float4*)(g_rj + (size_t)r * DD + col) = make_float4(o[0], o[1], o[2], o[3]);
        }
    }
}

// ---------------- obj GEMM: objTable = tanh(rj @ obj_W.T + obj_b) ----------------
__global__ void __launch_bounds__(256) objgemm_kernel(
    const float* __restrict__ obj_W, const float* __restrict__ obj_b, int R)
{
    __shared__ float As[32][36];
    __shared__ float Bs[32][68];
    int tid = threadIdx.x;
    int tx = tid & 15, ty = tid >> 4;
    int rbase = blockIdx.y * 32;
    int cbase = blockIdx.x * 64;
    float acc[2][4] = {};

    for (int k0 = 0; k0 < DD; k0 += 32) {
        {
            int ar = tid >> 3;
            int ac = (tid & 7) << 2;
            int gr = rbase + ar;
            float4 av = (gr < R) ? *(const float4*)(g_rj + (size_t)gr * DD + k0 + ac)
                                 : make_float4(0.f, 0.f, 0.f, 0.f);
            *(float4*)&As[ar][ac] = av;
        }
        #pragma unroll
        for (int i = 0; i < 2; i++) {
            int idx = tid + i * 256;
            int jj = idx >> 3;
            int kc = (idx & 7) << 2;
            float4 w4 = *(const float4*)(obj_W + (size_t)(cbase + jj) * DD + k0 + kc);
            Bs[kc + 0][jj] = w4.x;
            Bs[kc + 1][jj] = w4.y;
            Bs[kc + 2][jj] = w4.z;
            Bs[kc + 3][jj] = w4.w;
        }
        __syncthreads();
        #pragma unroll
        for (int kk = 0; kk < 32; kk++) {
            float a0 = As[ty][kk];
            float a1 = As[ty + 16][kk];
            float4 b = *(const float4*)&Bs[kk][tx * 4];
            acc[0][0] = fmaf(a0, b.x, acc[0][0]); acc[0][1] = fmaf(a0, b.y, acc[0][1]);
            acc[0][2] = fmaf(a0, b.z, acc[0][2]); acc[0][3] = fmaf(a0, b.w, acc[0][3]);
            acc[1][0] = fmaf(a1, b.x, acc[1][0]); acc[1][1] = fmaf(a1, b.y, acc[1][1]);
            acc[1][2] = fmaf(a1, b.z, acc[1][2]); acc[1][3] = fmaf(a1, b.w, acc[1][3]);
        }
        __syncthreads();
    }

    int col = cbase + tx * 4;
    float4 bv = *(const float4*)(obj_b + col);
    #pragma unroll
    for (int i = 0; i < 2; i++) {
        int r = rbase + ty + i * 16;
        if (r < R) {
            float4 v;
            v.x = tanhf(acc[i][0] + bv.x); v.y = tanhf(acc[i][1] + bv.y);
            v.z = tanhf(acc[i][2] + bv.z); v.w = tanhf(acc[i][3] + bv.w);
            *(float4*)(g_objTable + (size_t)r * DD + col) = v;
        }
    }
}

// ---------------- final assembly: 32 threads/row, 2 rows/thread ----------------
__device__ __forceinline__ void fetch_row(
    int c, long long n, int sd, const float* __restrict__ et, int lane,
    float4& a, float4& b)
{
    if (c >= 0) {
        if (c & OBJ_FLAG) {
            const float4* p = (const float4*)(g_objTable + (size_t)(c & (OBJ_FLAG - 1)) * DD);
            a = p[lane * 2]; b = p[lane * 2 + 1];
        } else {
            const float4* p = (const float4*)(et + (size_t)c * DD);
            a = __ldcs(p + lane * 2); b = __ldcs(p + lane * 2 + 1);
        }
    } else if ((int)n == sd) {
        const float4* p = (const float4*)g_sub;
        a = p[lane * 2]; b = p[lane * 2 + 1];
    } else {
        a = make_float4(0.f, 0.f, 0.f, 0.f);
        b = a;
    }
}

__global__ void __launch_bounds__(256) assemble_kernel(
    float* __restrict__ out, const float* __restrict__ entity_table,
    const int* __restrict__ seed_p, int N)
{
    long long gid = (long long)blockIdx.x * blockDim.x + threadIdx.x;
    int lane = (int)(gid & 31);
    long long i = gid >> 5;
    long long half = (N + 1) >> 1;
    if (i >= half) return;

    long long n0 = i, n1 = i + half;
    bool has1 = n1 < N;
    int sd = __ldg(seed_p);
    int c0 = g_src[n0];
    int c1 = has1 ? g_src[n1] : -1;

    float4 a0, b0, a1, b1;
    fetch_row(c0, n0, sd, entity_table, lane, a0, b0);
    if (has1) fetch_row(c1, n1, sd, entity_table, lane, a1, b1);

    float4* o0 = (float4*)out + n0 * (DD / 4);
    __stcs(o0 + lane * 2, a0);
    __stcs(o0 + lane * 2 + 1, b0);
    if (has1) {
        float4* o1 = (float4*)out + n1 * (DD / 4);
        __stcs(o1 + lane * 2, a1);
        __stcs(o1 + lane * 2 + 1, b1);
    }
}

// ---------------- launch ----------------
extern "C" void kernel_launch(void* const* d_in, const int* in_sizes, int n_in,
                              void* d_out, int out_size)
{
    const float* enc          = (const float*)d_in[0];
    const float* mask         = (const float*)d_in[1];
    const float* entity_table = (const float*)d_in[2];
    const float* rel_table    = (const float*)d_in[3];
    const float* W_ih         = (const float*)d_in[4];
    const float* W_hh         = (const float*)d_in[5];
    const float* b_ih         = (const float*)d_in[6];
    const float* b_hh         = (const float*)d_in[7];
    const float* sub_W        = (const float*)d_in[8];
    const float* sub_b        = (const float*)d_in[9];
    const float* obj_W        = (const float*)d_in[10];
    const float* obj_b        = (const float*)d_in[11];
    const int*   rel_ids      = (const int*)d_in[12];
    const int*   tail_ids     = (const int*)d_in[13];
    const int*   tails_state  = (const int*)d_in[14];
    const int*   origin_ids   = (const int*)d_in[15];
    const int*   seed_p       = (const int*)d_in[16];
    float*       out          = (float*)d_out;

    int E = in_sizes[12];
    int R = in_sizes[3] / DD;
    int N = out_size / DD;

    static cudaStream_t s2 = nullptr;
    static cudaEvent_t evFork = nullptr, evSrc = nullptr;
    if (!s2) {
        cudaStreamCreateWithFlags(&s2, cudaStreamNonBlocking);
        cudaEventCreateWithFlags(&evFork, cudaEventDisableTiming);
        cudaEventCreateWithFlags(&evSrc,  cudaEventDisableTiming);
    }

    int* srcp;
    cudaGetSymbolAddress((void**)&srcp, g_src);

    // ---- s2: src map (memset -1 -> scatter); seed handled inside assemble ----
    cudaEventRecord(evFork, 0);
    cudaStreamWaitEvent(s2, evFork, 0);
    cudaMemsetAsync(srcp, 0xFF, (size_t)N * sizeof(int), s2);
    scatter_kernel<<<(E + 511) / 512, 512, 0, s2>>>(tail_ids, tails_state, origin_ids, rel_ids, E);
    cudaEventRecord(evSrc, s2);

    // ---- s0: K1{sub+gi0+gh0} -> matvecD{r0+gi} -> relgemm -> objgemm ----
    matvec1_kernel<<<48, 512>>>(mask, enc, sub_W, sub_b, W_ih, W_hh, b_ih, b_hh);
    matvecD_kernel<<<96, 256>>>(W_ih, b_ih);
    relgemm_kernel<<<dim3(4, (R + 31) / 32), 256>>>(rel_table, W_hh, b_hh, R);
    objgemm_kernel<<<dim3(4, (R + 31) / 32), 256>>>(obj_W, obj_b, R);

    // ---- assemble (needs src map + objTable + g_sub) ----
    cudaStreamWaitEvent(0, evSrc, 0);
    long long half = ((long long)N + 1) >> 1;
    long long threads = half * 32;
    int asmBlocks = (int)((threads + 255) / 256);
    assemble_kernel<<<asmBlocks, 256>>>(out, entity_table, seed_p, N);
}

// round 17
// speedup vs baseline: 1.0619x; 1.0619x over previous
#include <cuda_runtime.h>
#include <math.h>

#define DD   256
#define DD3  768
#define OBJ_FLAG 0x40000000

// ---------------- device scratch ----------------
__device__ float g_sub[DD];                 // seed subject embedding
__device__ float g_gi0[DD3];                // enc @ W_ih.T + b_ih
__device__ float g_gh0[DD3];                // sub @ W_hh.T + b_hh
__device__ float g_gi[DD3];                 // r0 @ W_ih.T + b_ih
__device__ float g_rj[1024 * DD];           // GRU output per relation [R,256]
__device__ float g_objTable[1024 * DD];     // obj embedding per relation [R,256]
__device__ int   g_src[1 << 19];            // node -> source descriptor

__device__ __forceinline__ float sigm(float x) { return 1.0f / (1.0f + expf(-x)); }

// ---------------- matvec1: sub (rows 0..255) + gi0 (rows 256..1023) ----------------
__global__ void __launch_bounds__(256) matvec1_kernel(
    const float* __restrict__ mask, const float* __restrict__ enc,
    const float* __restrict__ sub_W, const float* __restrict__ sub_b,
    const float* __restrict__ W_ih, const float* __restrict__ b_ih)
{
    __shared__ float4 xm[64], xe[64];
    int tid = threadIdx.x, lane = tid & 31, warp = tid >> 5;
    if (tid < 64) { xm[tid] = ((const float4*)mask)[tid]; xe[tid] = ((const float4*)enc)[tid]; }
    __syncthreads();
    int grow = blockIdx.x * 8 + warp;            // 0..1023
    bool isSub = grow < DD;
    int row = isSub ? grow : grow - DD;
    const float4* w = (const float4*)((isSub ? sub_W : W_ih) + (size_t)row * DD);
    const float4* xv = isSub ? xm : xe;
    float acc = 0.f;
    #pragma unroll
    for (int i = 0; i < 2; i++) {
        int k = lane + i * 32;
        float4 wv = w[k], x4 = xv[k];
        acc += wv.x * x4.x + wv.y * x4.y + wv.z * x4.z + wv.w * x4.w;
    }
    #pragma unroll
    for (int o = 16; o > 0; o >>= 1) acc += __shfl_down_sync(~0u, acc, o);
    if (lane == 0) {
        if (isSub) g_sub[row] = tanhf(acc + sub_b[row]);
        else       g_gi0[row] = acc + b_ih[row];
    }
}

// ---------------- matvec2: gh0 = W_hh @ sub + b_hh (768 rows) ----------------
__global__ void __launch_bounds__(256) matvec2_kernel(
    const float* __restrict__ W_hh, const float* __restrict__ b_hh)
{
    __shared__ float4 xs[64];
    int tid = threadIdx.x, lane = tid & 31, warp = tid >> 5;
    if (tid < 64) xs[tid] = ((const float4*)g_sub)[tid];
    __syncthreads();
    int row = blockIdx.x * 8 + warp;             // 0..767
    const float4* w = (const float4*)(W_hh + (size_t)row * DD);
    float acc = 0.f;
    #pragma unroll
    for (int i = 0; i < 2; i++) {
        int k = lane + i * 32;
        float4 wv = w[k], x4 = xs[k];
        acc += wv.x * x4.x + wv.y * x4.y + wv.z * x4.z + wv.w * x4.w;
    }
    #pragma unroll
    for (int o = 16; o > 0; o >>= 1) acc += __shfl_down_sync(~0u, acc, o);
    if (lane == 0) g_gh0[row] = acc + b_hh[row];
}

// ---------------- matvecD: r0 (recomputed) then gi = W_ih @ r0 + b_ih ----------------
__global__ void __launch_bounds__(256) matvecD_kernel(
    const float* __restrict__ W_ih, const float* __restrict__ b_ih)
{
    __shared__ float r0s[DD];
    int tid = threadIdx.x, lane = tid & 31, warp = tid >> 5;
    {
        float gi_r = g_gi0[tid],          gh_r = g_gh0[tid];
        float gi_z = g_gi0[DD + tid],     gh_z = g_gh0[DD + tid];
        float gi_n = g_gi0[2 * DD + tid], gh_n = g_gh0[2 * DD + tid];
        float r = sigm(gi_r + gh_r);
        float z = sigm(gi_z + gh_z);
        float n = tanhf(gi_n + r * gh_n);
        r0s[tid] = (1.0f - z) * n + z * g_sub[tid];
    }
    __syncthreads();
    int row = blockIdx.x * 8 + warp;             // 0..767
    const float4* w = (const float4*)(W_ih + (size_t)row * DD);
    const float4* xv = (const float4*)r0s;
    float acc = 0.f;
    #pragma unroll
    for (int i = 0; i < 2; i++) {
        int k = lane + i * 32;
        float4 wv = w[k], x4 = xv[k];
        acc += wv.x * x4.x + wv.y * x4.y + wv.z * x4.z + wv.w * x4.w;
    }
    #pragma unroll
    for (int o = 16; o > 0; o >>= 1) acc += __shfl_down_sync(~0u, acc, o);
    if (lane == 0) g_gi[row] = acc + b_ih[row];
}

// ---------------- scatter ----------------
__global__ void __launch_bounds__(512) scatter_kernel(
    const int* __restrict__ tail_ids, const int* __restrict__ tails_state,
    const int* __restrict__ origin_ids, const int* __restrict__ rel_ids, int E)
{
    int e = blockIdx.x * blockDim.x + threadIdx.x;
    if (e >= E) return;
    int code = (__ldg(tails_state + e) == 1) ? __ldg(origin_ids + e)
                                             : (__ldg(rel_ids + e) | OBJ_FLAG);
    g_src[__ldg(tail_ids + e)] = code;
}

// ---------------- relgemm: k-split, 4-row register tiling ----------------
// grid (4, 32), 256 threads = 2 k-halves x (16 tx x 8 ry). Thread: 4 rows x 4 cols x 3 gates.
__global__ void __launch_bounds__(256) relgemm_kernel(
    const float* __restrict__ rel_table, const float* __restrict__ W_hh,
    const float* __restrict__ b_hh, int R)
{
    __shared__ float As[32][36];
    __shared__ float Bs[3][32][68];      // 26.1KB; reused as reduction buffer after mainloop
    int tid = threadIdx.x;
    int half = tid >> 7;                 // k-split half
    int t = tid & 127;
    int tx = t & 15;                     // 4 cols each
    int ry = t >> 4;                     // 0..7, 4 rows each
    int rbase = blockIdx.y * 32;
    int j0 = blockIdx.x * 64;
    int kb = half * 16;
    float acc[3][4][4] = {};

    for (int k0 = 0; k0 < DD; k0 += 32) {
        {   // A tile: 32 rows x 32 k (256 float4, 1/thread)
            int ar = tid >> 3;
            int ac = (tid & 7) << 2;
            int gr = rbase + ar;
            float4 av = (gr < R) ? *(const float4*)(rel_table + (size_t)gr * DD + k0 + ac)
                                 : make_float4(0.f, 0.f, 0.f, 0.f);
            *(float4*)&As[ar][ac] = av;
        }
        #pragma unroll
        for (int i = 0; i < 6; i++) {    // B tiles: 192 j-rows x 32 k, transposed store
            int idx = tid + i * 256;
            int jrow = idx >> 3;         // 0..191
            int kc = (idx & 7) << 2;
            int gate = jrow >> 6;
            int jj = jrow & 63;
            float4 w4 = *(const float4*)(W_hh + (size_t)(gate * DD + j0 + jj) * DD + k0 + kc);
            Bs[gate][kc + 0][jj] = w4.x;
            Bs[gate][kc + 1][jj] = w4.y;
            Bs[gate][kc + 2][jj] = w4.z;
            Bs[gate][kc + 3][jj] = w4.w;
        }
        __syncthreads();
        #pragma unroll
        for (int kk = 0; kk < 16; kk++) {
            int k = kb + kk;
            float a0 = As[ry * 4 + 0][k];
            float a1 = As[ry * 4 + 1][k];
            float a2 = As[ry * 4 + 2][k];
            float a3 = As[ry * 4 + 3][k];
            #pragma unroll
            for (int g = 0; g < 3; g++) {
                float4 b = *(const float4*)&Bs[g][k][tx * 4];
                acc[g][0][0] = fmaf(a0, b.x, acc[g][0][0]); acc[g][0][1] = fmaf(a0, b.y, acc[g][0][1]);
                acc[g][0][2] = fmaf(a0, b.z, acc[g][0][2]); acc[g][0][3] = fmaf(a0, b.w, acc[g][0][3]);
                acc[g][1][0] = fmaf(a1, b.x, acc[g][1][0]); acc[g][1][1] = fmaf(a1, b.y, acc[g][1][1]);
                acc[g][1][2] = fmaf(a1, b.z, acc[g][1][2]); acc[g][1][3] = fmaf(a1, b.w, acc[g][1][3]);
                acc[g][2][0] = fmaf(a2, b.x, acc[g][2][0]); acc[g][2][1] = fmaf(a2, b.y, acc[g][2][1]);
                acc[g][2][2] = fmaf(a2, b.z, acc[g][2][2]); acc[g][2][3] = fmaf(a2, b.w, acc[g][2][3]);
                acc[g][3][0] = fmaf(a3, b.x, acc[g][3][0]); acc[g][3][1] = fmaf(a3, b.y, acc[g][3][1]);
                acc[g][3][2] = fmaf(a3, b.z, acc[g][3][2]); acc[g][3][3] = fmaf(a3, b.w, acc[g][3][3]);
            }
        }
        __syncthreads();
    }

    // cross-half reduction (reuse Bs: 48 * 128 floats = 24KB)
    float* red = &Bs[0][0][0];
    if (half == 1) {
        #pragma unroll
        for (int g = 0; g < 3; g++)
            #pragma unroll
            for (int i = 0; i < 4; i++)
                #pragma unroll
                for (int q = 0; q < 4; q++)
                    red[(((g * 4 + i) * 4) + q) * 128 + t] = acc[g][i][q];
    }
    __syncthreads();
    if (half == 0) {
        #pragma unroll
        for (int g = 0; g < 3; g++)
            #pragma unroll
            for (int i = 0; i < 4; i++)
                #pragma unroll
                for (int q = 0; q < 4; q++)
                    acc[g][i][q] += red[(((g * 4 + i) * 4) + q) * 128 + t];

        // epilogue: gh + bias -> GRU gates -> g_rj (128 threads, 4 rows each)
        int col = j0 + tx * 4;
        float4 bhr = *(const float4*)(b_hh + col);
        float4 bhz = *(const float4*)(b_hh + DD + col);
        float4 bhn = *(const float4*)(b_hh + 2 * DD + col);
        float4 gir = *(const float4*)(g_gi + col);
        float4 giz = *(const float4*)(g_gi + DD + col);
        float4 gin = *(const float4*)(g_gi + 2 * DD + col);
        float gi_r[4] = { gir.x, gir.y, gir.z, gir.w };
        float gi_z[4] = { giz.x, giz.y, giz.z, giz.w };
        float gi_n[4] = { gin.x, gin.y, gin.z, gin.w };
        float bh_r[4] = { bhr.x, bhr.y, bhr.z, bhr.w };
        float bh_z[4] = { bhz.x, bhz.y, bhz.z, bhz.w };
        float bh_n[4] = { bhn.x, bhn.y, bhn.z, bhn.w };
        #pragma unroll
        for (int i = 0; i < 4; i++) {
            int r = rbase + ry * 4 + i;
            if (r < R) {
                float4 h = *(const float4*)(rel_table + (size_t)r * DD + col);
                float hh[4] = { h.x, h.y, h.z, h.w };
                float o[4];
                #pragma unroll
                for (int q = 0; q < 4; q++) {
                    float rr = sigm(gi_r[q] + acc[0][i][q] + bh_r[q]);
                    float zz = sigm(gi_z[q] + acc[1][i][q] + bh_z[q]);
                    float nn = tanhf(gi_n[q] + rr * (acc[2][i][q] + bh_n[q]));
                    o[q] = (1.f - zz) * nn + zz * hh[q];
                }
                *(float4*)(g_rj + (size_t)r * DD + col) = make_float4(o[0], o[1], o[2], o[3]);
            }
        }
    }
}

// ---------------- objgemm: k-split, 4-row register tiling ----------------
__global__ void __launch_bounds__(256) objgemm_kernel(
    const float* __restrict__ obj_W, const float* __restrict__ obj_b, int R)
{
    __shared__ float As[32][36];
    __shared__ float Bs[32][68];         // 8.7KB; reduction buffer (16*128 floats = 8KB) fits
    int tid = threadIdx.x;
    int half = tid >> 7;
    int t = tid & 127;
    int tx = t & 15;
    int ry = t >> 4;
    int rbase = blockIdx.y * 32;
    int cbase = blockIdx.x * 64;
    int kb = half * 16;
    float acc[4][4] = {};

    for (int k0 = 0; k0 < DD; k0 += 32) {
        {
            int ar = tid >> 3;
            int ac = (tid & 7) << 2;
            int gr = rbase + ar;
            float4 av = (gr < R) ? *(const float4*)(g_rj + (size_t)gr * DD + k0 + ac)
                                 : make_float4(0.f, 0.f, 0.f, 0.f);
            *(float4*)&As[ar][ac] = av;
        }
        #pragma unroll
        for (int i = 0; i < 2; i++) {    // 64 j-rows x 32 k, transposed store
            int idx = tid + i * 256;
            int jj = idx >> 3;
            int kc = (idx & 7) << 2;
            float4 w4 = *(const float4*)(obj_W + (size_t)(cbase + jj) * DD + k0 + kc);
            Bs[kc + 0][jj] = w4.x;
            Bs[kc + 1][jj] = w4.y;
            Bs[kc + 2][jj] = w4.z;
            Bs[kc + 3][jj] = w4.w;
        }
        __syncthreads();
        #pragma unroll
        for (int kk = 0; kk < 16; kk++) {
            int k = kb + kk;
            float a0 = As[ry * 4 + 0][k];
            float a1 = As[ry * 4 + 1][k];
            float a2 = As[ry * 4 + 2][k];
            float a3 = As[ry * 4 + 3][k];
            float4 b = *(const float4*)&Bs[k][tx * 4];
            acc[0][0] = fmaf(a0, b.x, acc[0][0]); acc[0][1] = fmaf(a0, b.y, acc[0][1]);
            acc[0][2] = fmaf(a0, b.z, acc[0][2]); acc[0][3] = fmaf(a0, b.w, acc[0][3]);
            acc[1][0] = fmaf(a1, b.x, acc[1][0]); acc[1][1] = fmaf(a1, b.y, acc[1][1]);
            acc[1][2] = fmaf(a1, b.z, acc[1][2]); acc[1][3] = fmaf(a1, b.w, acc[1][3]);
            acc[2][0] = fmaf(a2, b.x, acc[2][0]); acc[2][1] = fmaf(a2, b.y, acc[2][1]);
            acc[2][2] = fmaf(a2, b.z, acc[2][2]); acc[2][3] = fmaf(a2, b.w, acc[2][3]);
            acc[3][0] = fmaf(a3, b.x, acc[3][0]); acc[3][1] = fmaf(a3, b.y, acc[3][1]);
            acc[3][2] = fmaf(a3, b.z, acc[3][2]); acc[3][3] = fmaf(a3, b.w, acc[3][3]);
        }
        __syncthreads();
    }

    float* red = &Bs[0][0];
    if (half == 1) {
        #pragma unroll
        for (int i = 0; i < 4; i++)
            #pragma unroll
            for (int q = 0; q < 4; q++)
                red[(i * 4 + q) * 128 + t] = acc[i][q];
    }
    __syncthreads();
    if (half == 0) {
        #pragma unroll
        for (int i = 0; i < 4; i++)
            #pragma unroll
            for (int q = 0; q < 4; q++)
                acc[i][q] += red[(i * 4 + q) * 128 + t];

        int col = cbase + tx * 4;
        float4 bv = *(const float4*)(obj_b + col);
        float bb[4] = { bv.x, bv.y, bv.z, bv.w };
        #pragma unroll
        for (int i = 0; i < 4; i++) {
            int r = rbase + ry * 4 + i;
            if (r < R) {
                float4 v;
                v.x = tanhf(acc[i][0] + bb[0]); v.y = tanhf(acc[i][1] + bb[1]);
                v.z = tanhf(acc[i][2] + bb[2]); v.w = tanhf(acc[i][3] + bb[3]);
                *(float4*)(g_objTable + (size_t)r * DD + col) = v;
            }
        }
    }
}

// ---------------- final assembly: 32 threads/row, 2 rows/thread ----------------
__device__ __forceinline__ void fetch_row(
    int c, long long n, int sd, const float* __restrict__ et, int lane,
    float4& a, float4& b)
{
    if (c >= 0) {
        if (c & OBJ_FLAG) {
            const float4* p = (const float4*)(g_objTable + (size_t)(c & (OBJ_FLAG - 1)) * DD);
            a = p[lane * 2]; b = p[lane * 2 + 1];
        } else {
            const float4* p = (const float4*)(et + (size_t)c * DD);
            a = __ldcs(p + lane * 2); b = __ldcs(p + lane * 2 + 1);
        }
    } else if ((int)n == sd) {
        const float4* p = (const float4*)g_sub;
        a = p[lane * 2]; b = p[lane * 2 + 1];
    } else {
        a = make_float4(0.f, 0.f, 0.f, 0.f);
        b = a;
    }
}

__global__ void __launch_bounds__(256) assemble_kernel(
    float* __restrict__ out, const float* __restrict__ entity_table,
    const int* __restrict__ seed_p, int N)
{
    long long gid = (long long)blockIdx.x * blockDim.x + threadIdx.x;
    int lane = (int)(gid & 31);
    long long i = gid >> 5;
    long long half = (N + 1) >> 1;
    if (i >= half) return;

    long long n0 = i, n1 = i + half;
    bool has1 = n1 < N;
    int sd = __ldg(seed_p);
    int c0 = g_src[n0];
    int c1 = has1 ? g_src[n1] : -1;

    float4 a0, b0, a1, b1;
    fetch_row(c0, n0, sd, entity_table, lane, a0, b0);
    if (has1) fetch_row(c1, n1, sd, entity_table, lane, a1, b1);

    float4* o0 = (float4*)out + n0 * (DD / 4);
    __stcs(o0 + lane * 2, a0);
    __stcs(o0 + lane * 2 + 1, b0);
    if (has1) {
        float4* o1 = (float4*)out + n1 * (DD / 4);
        __stcs(o1 + lane * 2, a1);
        __stcs(o1 + lane * 2 + 1, b1);
    }
}

// ---------------- launch ----------------
extern "C" void kernel_launch(void* const* d_in, const int* in_sizes, int n_in,
                              void* d_out, int out_size)
{
    const float* enc          = (const float*)d_in[0];
    const float* mask         = (const float*)d_in[1];
    const float* entity_table = (const float*)d_in[2];
    const float* rel_table    = (const float*)d_in[3];
    const float* W_ih         = (const float*)d_in[4];
    const float* W_hh         = (const float*)d_in[5];
    const float* b_ih         = (const float*)d_in[6];
    const float* b_hh         = (const float*)d_in[7];
    const float* sub_W        = (const float*)d_in[8];
    const float* sub_b        = (const float*)d_in[9];
    const float* obj_W        = (const float*)d_in[10];
    const float* obj_b        = (const float*)d_in[11];
    const int*   rel_ids      = (const int*)d_in[12];
    const int*   tail_ids     = (const int*)d_in[13];
    const int*   tails_state  = (const int*)d_in[14];
    const int*   origin_ids   = (const int*)d_in[15];
    const int*   seed_p       = (const int*)d_in[16];
    float*       out          = (float*)d_out;

    int E = in_sizes[12];
    int R = in_sizes[3] / DD;
    int N = out_size / DD;

    static cudaStream_t s2 = nullptr;
    static cudaEvent_t evFork = nullptr, evSrc = nullptr;
    if (!s2) {
        cudaStreamCreateWithFlags(&s2, cudaStreamNonBlocking);
        cudaEventCreateWithFlags(&evFork, cudaEventDisableTiming);
        cudaEventCreateWithFlags(&evSrc,  cudaEventDisableTiming);
    }

    int* srcp;
    cudaGetSymbolAddress((void**)&srcp, g_src);

    // ---- s2: src map (memset -1 -> scatter); seed handled inside assemble ----
    cudaEventRecord(evFork, 0);
    cudaStreamWaitEvent(s2, evFork, 0);
    cudaMemsetAsync(srcp, 0xFF, (size_t)N * sizeof(int), s2);
    scatter_kernel<<<(E + 511) / 512, 512, 0, s2>>>(tail_ids, tails_state, origin_ids, rel_ids, E);
    cudaEventRecord(evSrc, s2);

    // ---- s0: matvec1{sub+gi0} -> matvec2{gh0} -> matvecD{r0+gi} -> relgemm -> objgemm ----
    matvec1_kernel<<<128, 256>>>(mask, enc, sub_W, sub_b, W_ih, b_ih);
    matvec2_kernel<<<96, 256>>>(W_hh, b_hh);
    matvecD_kernel<<<96, 256>>>(W_ih, b_ih);
    relgemm_kernel<<<dim3(4, (R + 31) / 32), 256>>>(rel_table, W_hh, b_hh, R);
    objgemm_kernel<<<dim3(4, (R + 31) / 32), 256>>>(obj_W, obj_b, R);

    // ---- assemble (needs src map + objTable + g_sub) ----
    cudaStreamWaitEvent(0, evSrc, 0);
    long long half = ((long long)N + 1) >> 1;
    long long threads = half * 32;
    int asmBlocks = (int)((threads + 255) / 256);
    assemble_kernel<<<asmBlocks, 256>>>(out, entity_table, seed_p, N);
}